// round 5
// baseline (speedup 1.0000x reference)
#include <cuda_runtime.h>
#include <cstddef>

// B=4096, T=256, I=6, H=64, gates=3H=192, 2 GRU layers + FC(H->1)
#define T_STEPS 256
#define I_DIM   6
#define HDIM    64
#define G3      192
#define BB      32      // batches per CTA
#define NT      512     // 4 batch-groups x 2 k-halves x 64 units
#define NBPT    8       // batches per thread
#define PW      68      // weight row pitch (floats): conflict-free LDS.128
#define KH      32      // k-half width
#define NCTA    128     // 4096 / 32

typedef unsigned long long u64;

// Packed fp32x2 FMA: acc.{x,y} += a.{x,y} * b.{x,y}  (SASS FFMA2, PTX-only)
#define FFMA2(acc, a, b) \
    asm("fma.rn.f32x2 %0, %1, %2, %0;" : "+l"(acc) : "l"(a), "l"(b))

union F4U { float4 f; u64 u[2]; };
union F2U { float2 f; u64 u; };

struct SmemLayout {
    float  Whh0[G3 * PW];
    float  Wih1[G3 * PW];
    float  Whh1[G3 * PW];
    float  Wih0[G3 * 8];      // pitch 8 -> float2 pairs (cols 6,7 zero)
    float  bih0[G3];
    float  bhh0[G3];
    float  bih1[G3];
    float  bhh1[G3];
    float  h1[2][BB][HDIM];   // ping-pong hidden, layer 0
    float  h2[2][BB][HDIM];   // ping-pong hidden, layer 1
    float  xs[2][BB][8];
    float2 partRZ[BB][HDIM];  // kh=1 partials: (r,z)
    float  partN [BB][HDIM];  // kh=1 partials: hn
    float  wfc[HDIM];
    float  bfc;
};

__device__ __forceinline__ float sigf(float v) {
    return __fdividef(1.0f, 1.0f + __expf(-v));
}
__device__ __forceinline__ float hsum(u64 p) {
    F2U t; t.u = p;
    return t.f.x + t.f.y;
}

__global__ __launch_bounds__(NT, 1) void gru_fused_kernel(
    const float* __restrict__ x,
    const float* __restrict__ W_ih0, const float* __restrict__ W_hh0,
    const float* __restrict__ b_ih0, const float* __restrict__ b_hh0,
    const float* __restrict__ W_ih1, const float* __restrict__ W_hh1,
    const float* __restrict__ b_ih1, const float* __restrict__ b_hh1,
    const float* __restrict__ W_fc,  const float* __restrict__ b_fc,
    float* __restrict__ out)
{
    extern __shared__ float smem_raw[];
    SmemLayout& s = *reinterpret_cast<SmemLayout*>(smem_raw);

    const int tid = threadIdx.x;
    const int b0  = blockIdx.x * BB;

    // ---- Stage weights into SMEM ----
    for (int i = tid; i < G3 * HDIM; i += NT) {
        int r = i >> 6, c = i & 63;
        s.Whh0[r * PW + c] = W_hh0[i];
        s.Wih1[r * PW + c] = W_ih1[i];
        s.Whh1[r * PW + c] = W_hh1[i];
    }
    for (int i = tid; i < G3 * 8; i += NT) s.Wih0[i] = 0.0f;
    for (int i = tid; i < BB * 8 * 2; i += NT) ((float*)s.xs)[i] = 0.0f;
    __syncthreads();
    for (int i = tid; i < G3 * I_DIM; i += NT)
        s.Wih0[(i / I_DIM) * 8 + (i % I_DIM)] = W_ih0[i];
    for (int i = tid; i < G3; i += NT) {
        s.bih0[i] = b_ih0[i];
        s.bhh0[i] = b_hh0[i];
        s.bih1[i] = b_ih1[i];
        s.bhh1[i] = b_hh1[i];
    }
    for (int i = tid; i < BB * HDIM; i += NT) {
        int b = i >> 6, c = i & 63;
        s.h1[0][b][c] = 0.0f;
        s.h2[0][b][c] = 0.0f;
    }
    if (tid < HDIM) s.wfc[tid] = W_fc[tid];
    if (tid == 0)   s.bfc = b_fc[0];

    // x prefetch lanes (one per (batch, input-dim))
    const bool is_pref_lane = (tid < BB * I_DIM);
    const int  lb = is_pref_lane ? (tid / I_DIM) : 0;
    const int  li = is_pref_lane ? (tid % I_DIM) : 0;
    const float* xlane = x + (size_t)(b0 + lb) * T_STEPS * I_DIM + li;
    if (is_pref_lane) s.xs[0][lb][li] = xlane[0];
    __syncthreads();

    // Mapping: bg = tid>>7 (0..3) -> batches bg*8..bg*8+7
    //          kh = (tid>>6)&1   -> k-half (0: k 0..31, 1: k 32..63)
    //          gg = tid&63       -> hidden unit; gates gg, gg+64, gg+128
    const int gg  = tid & 63;
    const int kh  = (tid >> 6) & 1;
    const int bg  = tid >> 7;
    const int bb0 = bg * NBPT;
    const int kb  = kh * KH;
    const int gr = gg, gz = gg + 64, gn = gg + 128;

    // Biases, applied once by the kh=0 combiner at activation time
    const float brC  = s.bih0[gr] + s.bhh0[gr];
    const float bzC  = s.bih0[gz] + s.bhh0[gz];
    const float bxn0 = s.bih0[gn], bhn0 = s.bhh0[gn];
    const float brC1 = s.bih1[gr] + s.bhh1[gr];
    const float bzC1 = s.bih1[gz] + s.bhh1[gz];
    const float bxn1 = s.bih1[gn], bhn1 = s.bhh1[gn];

    // Per-batch accumulators {r, z, xn, hn}, each an fp32x2 k-pair
    u64 aR[NBPT], aZ[NBPT], aXN[NBPT], aHN[NBPT];

    for (int t = 0; t < T_STEPS; ++t) {
        const int cur = t & 1, nxt = cur ^ 1;

        float xpref = 0.0f;
        const bool do_pref = is_pref_lane && (t + 1 < T_STEPS);
        if (do_pref) xpref = xlane[(size_t)(t + 1) * I_DIM];

        // ================= Layer 0 =================
        #pragma unroll
        for (int b = 0; b < NBPT; ++b) {
            aR[b] = 0ull; aZ[b] = 0ull; aXN[b] = 0ull; aHN[b] = 0ull;
        }
        #pragma unroll 2
        for (int k = 0; k < KH; k += 4) {
            F4U w0; w0.f = *(const float4*)&s.Whh0[gr * PW + kb + k];
            F4U w1; w1.f = *(const float4*)&s.Whh0[gz * PW + kb + k];
            F4U w2; w2.f = *(const float4*)&s.Whh0[gn * PW + kb + k];
            #pragma unroll
            for (int b = 0; b < NBPT; ++b) {
                F4U h; h.f = *(const float4*)&s.h1[cur][bb0 + b][kb + k];
                FFMA2(aR[b],  h.u[0], w0.u[0]);
                FFMA2(aR[b],  h.u[1], w0.u[1]);
                FFMA2(aZ[b],  h.u[0], w1.u[0]);
                FFMA2(aZ[b],  h.u[1], w1.u[1]);
                FFMA2(aHN[b], h.u[0], w2.u[0]);
                FFMA2(aHN[b], h.u[1], w2.u[1]);
            }
        }
        if (kh == 0) {
            // input GEMV (I=6 -> 3 packed pairs); only the kh=0 half does it
            #pragma unroll
            for (int kp = 0; kp < 3; ++kp) {
                F2U w0; w0.f = *(const float2*)&s.Wih0[gr * 8 + 2 * kp];
                F2U w1; w1.f = *(const float2*)&s.Wih0[gz * 8 + 2 * kp];
                F2U w2; w2.f = *(const float2*)&s.Wih0[gn * 8 + 2 * kp];
                #pragma unroll
                for (int b = 0; b < NBPT; ++b) {
                    F2U xv; xv.f = *(const float2*)&s.xs[cur][bb0 + b][2 * kp];
                    FFMA2(aR[b],  xv.u, w0.u);
                    FFMA2(aZ[b],  xv.u, w1.u);
                    FFMA2(aXN[b], xv.u, w2.u);
                }
            }
        } else {
            // publish upper-half partials
            #pragma unroll
            for (int b = 0; b < NBPT; ++b) {
                s.partRZ[bb0 + b][gg] = make_float2(hsum(aR[b]), hsum(aZ[b]));
                s.partN [bb0 + b][gg] = hsum(aHN[b]);
            }
        }
        __syncthreads();   // partials ready
        if (kh == 0) {
            #pragma unroll
            for (int b = 0; b < NBPT; ++b) {
                float2 prz = s.partRZ[bb0 + b][gg];
                float  phn = s.partN [bb0 + b][gg];
                float r  = sigf(hsum(aR[b]) + prz.x + brC);
                float z  = sigf(hsum(aZ[b]) + prz.y + bzC);
                float hn = hsum(aHN[b]) + phn + bhn0;
                float n  = tanhf(fmaf(r, hn, hsum(aXN[b]) + bxn0));
                float hp = s.h1[cur][bb0 + b][gg];
                s.h1[nxt][bb0 + b][gg] = fmaf(z, hp - n, n);
            }
        }
        if (do_pref) s.xs[nxt][lb][li] = xpref;
        __syncthreads();   // h1[nxt] complete

        // ================= Layer 1 =================
        // input = h1[nxt]; recurrent state = h2[cur]. Both GEMVs k-split.
        #pragma unroll
        for (int b = 0; b < NBPT; ++b) {
            aR[b] = 0ull; aZ[b] = 0ull; aXN[b] = 0ull; aHN[b] = 0ull;
        }
        for (int k = 0; k < KH; k += 4) {   // no forced unroll: live-set cap
            F4U u0; u0.f = *(const float4*)&s.Wih1[gr * PW + kb + k];
            F4U u1; u1.f = *(const float4*)&s.Wih1[gz * PW + kb + k];
            F4U u2; u2.f = *(const float4*)&s.Wih1[gn * PW + kb + k];
            F4U v0; v0.f = *(const float4*)&s.Whh1[gr * PW + kb + k];
            F4U v1; v1.f = *(const float4*)&s.Whh1[gz * PW + kb + k];
            F4U v2; v2.f = *(const float4*)&s.Whh1[gn * PW + kb + k];
            #pragma unroll
            for (int b = 0; b < NBPT; ++b) {
                F4U p; p.f = *(const float4*)&s.h1[nxt][bb0 + b][kb + k];
                F4U q; q.f = *(const float4*)&s.h2[cur][bb0 + b][kb + k];
                FFMA2(aR[b],  p.u[0], u0.u[0]);
                FFMA2(aR[b],  p.u[1], u0.u[1]);
                FFMA2(aZ[b],  p.u[0], u1.u[0]);
                FFMA2(aZ[b],  p.u[1], u1.u[1]);
                FFMA2(aXN[b], p.u[0], u2.u[0]);
                FFMA2(aXN[b], p.u[1], u2.u[1]);
                FFMA2(aR[b],  q.u[0], v0.u[0]);
                FFMA2(aR[b],  q.u[1], v0.u[1]);
                FFMA2(aZ[b],  q.u[0], v1.u[0]);
                FFMA2(aZ[b],  q.u[1], v1.u[1]);
                FFMA2(aHN[b], q.u[0], v2.u[0]);
                FFMA2(aHN[b], q.u[1], v2.u[1]);
            }
        }
        if (kh == 1) {
            // Publish partials. xn needs a 4th slot: use h2[nxt][b][gg] as
            // scratch — for each (b,gg) exactly one kh=1 writer here, one
            // kh=0 reader after the barrier, and that same kh=0 thread then
            // overwrites the location with the final h. No other reader
            // touches h2[nxt] this step (GEMVs read h2[cur] only).
            #pragma unroll
            for (int b = 0; b < NBPT; ++b) {
                s.partRZ[bb0 + b][gg] = make_float2(hsum(aR[b]), hsum(aZ[b]));
                s.partN [bb0 + b][gg] = hsum(aHN[b]);
                s.h2[nxt][bb0 + b][gg] = hsum(aXN[b]);
            }
        }
        __syncthreads();   // partials ready
        if (kh == 0) {
            #pragma unroll
            for (int b = 0; b < NBPT; ++b) {
                float2 prz = s.partRZ[bb0 + b][gg];
                float  phn = s.partN [bb0 + b][gg];
                float  pxn = s.h2[nxt][bb0 + b][gg];
                float r  = sigf(hsum(aR[b]) + prz.x + brC1);
                float z  = sigf(hsum(aZ[b]) + prz.y + bzC1);
                float hn = hsum(aHN[b]) + phn + bhn1;
                float n  = tanhf(fmaf(r, hn, hsum(aXN[b]) + pxn + bxn1));
                float hp = s.h2[cur][bb0 + b][gg];
                s.h2[nxt][bb0 + b][gg] = fmaf(z, hp - n, n);
            }
        }
        __syncthreads();   // h2[nxt] complete
    }

    // ---- Final FC ----
    const int fin = T_STEPS & 1;
    if (tid < BB) {
        float acc = s.bfc;
        #pragma unroll 8
        for (int k = 0; k < HDIM; ++k)
            acc = fmaf(s.h2[fin][tid][k], s.wfc[k], acc);
        out[b0 + tid] = acc;
    }
}

extern "C" void kernel_launch(void* const* d_in, const int* in_sizes, int n_in,
                              void* d_out, int out_size)
{
    const float* x     = (const float*)d_in[0];
    const float* W_ih0 = (const float*)d_in[1];
    const float* W_hh0 = (const float*)d_in[2];
    const float* b_ih0 = (const float*)d_in[3];
    const float* b_hh0 = (const float*)d_in[4];
    const float* W_ih1 = (const float*)d_in[5];
    const float* W_hh1 = (const float*)d_in[6];
    const float* b_ih1 = (const float*)d_in[7];
    const float* b_hh1 = (const float*)d_in[8];
    const float* W_fc  = (const float*)d_in[9];
    const float* b_fc  = (const float*)d_in[10];
    float* out = (float*)d_out;

    (void)in_sizes; (void)n_in; (void)out_size;

    static_assert(sizeof(SmemLayout) < 227 * 1024, "smem over budget");
    cudaFuncSetAttribute(gru_fused_kernel,
                         cudaFuncAttributeMaxDynamicSharedMemorySize,
                         (int)sizeof(SmemLayout));

    gru_fused_kernel<<<NCTA, NT, sizeof(SmemLayout)>>>(
        x, W_ih0, W_hh0, b_ih0, b_hh0,
        W_ih1, W_hh1, b_ih1, b_hh1,
        W_fc, b_fc, out);
}

// round 7
// speedup vs baseline: 1.2072x; 1.2072x over previous
#include <cuda_runtime.h>
#include <cstddef>

// B=4096, T=256, I=6, H=64, gates=3H=192, 2 GRU layers + FC(H->1)
#define T_STEPS 256
#define I_DIM   6
#define HDIM    64
#define G3      192
#define BB      32      // batches per CTA
#define NT      256     // 64 units x 4 batch-groups
#define NBPT    8       // batches per thread
#define PW      68      // weight row pitch (floats): conflict-free LDS.128
#define NCTA    128     // 4096 / 32

typedef unsigned long long u64;

// Packed fp32x2 FMA: acc.{x,y} += a.{x,y} * b.{x,y}  (SASS FFMA2, PTX-only)
#define FFMA2(acc, a, b) \
    asm("fma.rn.f32x2 %0, %1, %2, %0;" : "+l"(acc) : "l"(a), "l"(b))

union F4U { float4 f; u64 u[2]; };
union F2U { float2 f; u64 u; };

struct SmemLayout {
    float Whh0[G3 * PW];
    float Wih1[G3 * PW];
    float Whh1[G3 * PW];
    float Wih0[G3 * 8];     // pitch 8 (I=6 used) -> float2-aligned pairs
    float bih0[G3];
    float bhh0[G3];
    float bih1[G3];
    float bhh1[G3];
    float h1[2][BB][HDIM];  // ping-pong hidden state, layer 0
    float h2[2][BB][HDIM];  // ping-pong hidden state, layer 1
    float xs[2][BB][8];     // pitch 8 for float2 pairing
    float wfc[HDIM];
    float bfc;
};

__device__ __forceinline__ float sigf(float v) {
    return __fdividef(1.0f, 1.0f + __expf(-v));
}
// tanh via MUFU exp: short dependency chain (vs ~25-instr libdevice tanhf).
// Clamp keeps e^{2x} finite; |x|>15 is fully saturated in fp32 anyway.
__device__ __forceinline__ float tanhfast(float v) {
    float c = fminf(fmaxf(v, -15.0f), 15.0f);
    float e = __expf(2.0f * c);
    return __fdividef(e - 1.0f, e + 1.0f);
}
__device__ __forceinline__ float hsum(u64 p) {
    F2U t; t.u = p;
    return t.f.x + t.f.y;
}
__device__ __forceinline__ u64 packbias(float b) {
    F2U t; t.f = make_float2(b, 0.0f);
    return t.u;
}

__global__ __launch_bounds__(NT) void gru_fused_kernel(
    const float* __restrict__ x,
    const float* __restrict__ W_ih0, const float* __restrict__ W_hh0,
    const float* __restrict__ b_ih0, const float* __restrict__ b_hh0,
    const float* __restrict__ W_ih1, const float* __restrict__ W_hh1,
    const float* __restrict__ b_ih1, const float* __restrict__ b_hh1,
    const float* __restrict__ W_fc,  const float* __restrict__ b_fc,
    float* __restrict__ out)
{
    extern __shared__ float smem_raw[];
    SmemLayout& s = *reinterpret_cast<SmemLayout*>(smem_raw);

    const int tid = threadIdx.x;
    const int b0  = blockIdx.x * BB;

    // ---- Stage weights into SMEM ----
    for (int i = tid; i < G3 * HDIM; i += NT) {
        int r = i >> 6, c = i & 63;
        s.Whh0[r * PW + c] = W_hh0[i];
        s.Wih1[r * PW + c] = W_ih1[i];
        s.Whh1[r * PW + c] = W_hh1[i];
    }
    for (int i = tid; i < G3 * 8; i += NT) s.Wih0[i] = 0.0f;   // pad
    for (int i = tid; i < BB * 8 * 2; i += NT) ((float*)s.xs)[i] = 0.0f;
    __syncthreads();
    for (int i = tid; i < G3 * I_DIM; i += NT)
        s.Wih0[(i / I_DIM) * 8 + (i % I_DIM)] = W_ih0[i];
    for (int i = tid; i < G3; i += NT) {
        s.bih0[i] = b_ih0[i];
        s.bhh0[i] = b_hh0[i];
        s.bih1[i] = b_ih1[i];
        s.bhh1[i] = b_hh1[i];
    }
    for (int i = tid; i < BB * HDIM; i += NT) {
        int b = i >> 6, c = i & 63;
        s.h1[0][b][c] = 0.0f;
        s.h2[0][b][c] = 0.0f;
    }
    if (tid < HDIM) s.wfc[tid] = W_fc[tid];
    if (tid == 0)   s.bfc = b_fc[0];

    // x prefetch lanes (one per (batch, input-dim))
    const bool is_pref_lane = (tid < BB * I_DIM);
    const int  lb = is_pref_lane ? (tid / I_DIM) : 0;
    const int  li = is_pref_lane ? (tid % I_DIM) : 0;
    const float* xlane = x + (size_t)(b0 + lb) * T_STEPS * I_DIM + li;
    if (is_pref_lane) s.xs[0][lb][li] = xlane[0];
    __syncthreads();

    // Mapping: gg = hidden unit (0..63); bg = tid>>6 (0..3) -> 8 batches each.
    const int gg  = tid & 63;
    const int bg  = tid >> 6;
    const int bb0 = bg * NBPT;
    const int gr = gg, gz = gg + 64, gn = gg + 128;

    // Bias-seeded accumulator inits (combined where gates allow)
    const u64 iR0 = packbias(s.bih0[gr] + s.bhh0[gr]);
    const u64 iZ0 = packbias(s.bih0[gz] + s.bhh0[gz]);
    const u64 iXN0 = packbias(s.bih0[gn]);
    const u64 iHN0 = packbias(s.bhh0[gn]);
    const u64 iR1 = packbias(s.bih1[gr] + s.bhh1[gr]);
    const u64 iZ1 = packbias(s.bih1[gz] + s.bhh1[gz]);
    const u64 iXN1 = packbias(s.bih1[gn]);
    const u64 iHN1 = packbias(s.bhh1[gn]);

    u64 accX[NBPT][3], accH[NBPT][3];

    for (int t = 0; t < T_STEPS; ++t) {
        const int cur = t & 1, nxt = cur ^ 1;

        float xpref = 0.0f;
        const bool do_pref = is_pref_lane && (t + 1 < T_STEPS);
        if (do_pref) xpref = xlane[(size_t)(t + 1) * I_DIM];

        // ================= Layer 0 =================
        #pragma unroll
        for (int b = 0; b < NBPT; ++b) {
            accX[b][0] = iR0;  accX[b][1] = iZ0;  accX[b][2] = iXN0;
            accH[b][0] = 0ull; accH[b][1] = 0ull; accH[b][2] = iHN0;
        }
        // input GEMV first: its LDS latency overlaps the weight warm-up
        #pragma unroll
        for (int kp = 0; kp < 3; ++kp) {
            F2U w0; w0.f = *(const float2*)&s.Wih0[gr * 8 + 2 * kp];
            F2U w1; w1.f = *(const float2*)&s.Wih0[gz * 8 + 2 * kp];
            F2U w2; w2.f = *(const float2*)&s.Wih0[gn * 8 + 2 * kp];
            #pragma unroll
            for (int b = 0; b < NBPT; ++b) {
                F2U xv; xv.f = *(const float2*)&s.xs[cur][bb0 + b][2 * kp];
                FFMA2(accX[b][0], xv.u, w0.u);
                FFMA2(accX[b][1], xv.u, w1.u);
                FFMA2(accX[b][2], xv.u, w2.u);
            }
        }
        // recurrent GEMV
        #pragma unroll 2
        for (int k = 0; k < HDIM; k += 4) {
            F4U w0; w0.f = *(const float4*)&s.Whh0[gr * PW + k];
            F4U w1; w1.f = *(const float4*)&s.Whh0[gz * PW + k];
            F4U w2; w2.f = *(const float4*)&s.Whh0[gn * PW + k];
            #pragma unroll
            for (int b = 0; b < NBPT; ++b) {
                F4U h; h.f = *(const float4*)&s.h1[cur][bb0 + b][k];
                FFMA2(accH[b][0], h.u[0], w0.u[0]);
                FFMA2(accH[b][0], h.u[1], w0.u[1]);
                FFMA2(accH[b][1], h.u[0], w1.u[0]);
                FFMA2(accH[b][1], h.u[1], w1.u[1]);
                FFMA2(accH[b][2], h.u[0], w2.u[0]);
                FFMA2(accH[b][2], h.u[1], w2.u[1]);
            }
        }
        #pragma unroll
        for (int b = 0; b < NBPT; ++b) {
            float r = sigf(hsum(accX[b][0]) + hsum(accH[b][0]));
            float z = sigf(hsum(accX[b][1]) + hsum(accH[b][1]));
            float n = tanhfast(fmaf(r, hsum(accH[b][2]), hsum(accX[b][2])));
            float hp = s.h1[cur][bb0 + b][gg];
            s.h1[nxt][bb0 + b][gg] = fmaf(z, hp - n, n);
        }
        if (do_pref) s.xs[nxt][lb][li] = xpref;
        __syncthreads();   // h1[nxt] complete

        // ================= Layer 1 =================
        #pragma unroll
        for (int b = 0; b < NBPT; ++b) {
            accX[b][0] = iR1;  accX[b][1] = iZ1;  accX[b][2] = iXN1;
            accH[b][0] = 0ull; accH[b][1] = 0ull; accH[b][2] = iHN1;
        }
        #pragma unroll 2
        for (int k = 0; k < HDIM; k += 4) {
            F4U u0; u0.f = *(const float4*)&s.Wih1[gr * PW + k];
            F4U u1; u1.f = *(const float4*)&s.Wih1[gz * PW + k];
            F4U u2; u2.f = *(const float4*)&s.Wih1[gn * PW + k];
            F4U v0; v0.f = *(const float4*)&s.Whh1[gr * PW + k];
            F4U v1; v1.f = *(const float4*)&s.Whh1[gz * PW + k];
            F4U v2; v2.f = *(const float4*)&s.Whh1[gn * PW + k];
            #pragma unroll
            for (int b = 0; b < NBPT; ++b) {
                F4U p; p.f = *(const float4*)&s.h1[nxt][bb0 + b][k];
                F4U q; q.f = *(const float4*)&s.h2[cur][bb0 + b][k];
                FFMA2(accX[b][0], p.u[0], u0.u[0]);
                FFMA2(accX[b][0], p.u[1], u0.u[1]);
                FFMA2(accX[b][1], p.u[0], u1.u[0]);
                FFMA2(accX[b][1], p.u[1], u1.u[1]);
                FFMA2(accX[b][2], p.u[0], u2.u[0]);
                FFMA2(accX[b][2], p.u[1], u2.u[1]);
                FFMA2(accH[b][0], q.u[0], v0.u[0]);
                FFMA2(accH[b][0], q.u[1], v0.u[1]);
                FFMA2(accH[b][1], q.u[0], v1.u[0]);
                FFMA2(accH[b][1], q.u[1], v1.u[1]);
                FFMA2(accH[b][2], q.u[0], v2.u[0]);
                FFMA2(accH[b][2], q.u[1], v2.u[1]);
            }
        }
        #pragma unroll
        for (int b = 0; b < NBPT; ++b) {
            float r = sigf(hsum(accX[b][0]) + hsum(accH[b][0]));
            float z = sigf(hsum(accX[b][1]) + hsum(accH[b][1]));
            float n = tanhfast(fmaf(r, hsum(accH[b][2]), hsum(accX[b][2])));
            float hp = s.h2[cur][bb0 + b][gg];
            s.h2[nxt][bb0 + b][gg] = fmaf(z, hp - n, n);
        }
        __syncthreads();   // h2[nxt] complete
    }

    // ---- Final FC ----
    const int fin = T_STEPS & 1;
    if (tid < BB) {
        float acc = s.bfc;
        #pragma unroll 8
        for (int k = 0; k < HDIM; ++k)
            acc = fmaf(s.h2[fin][tid][k], s.wfc[k], acc);
        out[b0 + tid] = acc;
    }
}

extern "C" void kernel_launch(void* const* d_in, const int* in_sizes, int n_in,
                              void* d_out, int out_size)
{
    const float* x     = (const float*)d_in[0];
    const float* W_ih0 = (const float*)d_in[1];
    const float* W_hh0 = (const float*)d_in[2];
    const float* b_ih0 = (const float*)d_in[3];
    const float* b_hh0 = (const float*)d_in[4];
    const float* W_ih1 = (const float*)d_in[5];
    const float* W_hh1 = (const float*)d_in[6];
    const float* b_ih1 = (const float*)d_in[7];
    const float* b_hh1 = (const float*)d_in[8];
    const float* W_fc  = (const float*)d_in[9];
    const float* b_fc  = (const float*)d_in[10];
    float* out = (float*)d_out;

    (void)in_sizes; (void)n_in; (void)out_size;

    static_assert(sizeof(SmemLayout) < 227 * 1024, "smem over budget");
    cudaFuncSetAttribute(gru_fused_kernel,
                         cudaFuncAttributeMaxDynamicSharedMemorySize,
                         (int)sizeof(SmemLayout));

    gru_fused_kernel<<<NCTA, NT, sizeof(SmemLayout)>>>(
        x, W_ih0, W_hh0, b_ih0, b_hh0,
        W_ih1, W_hh1, b_ih1, b_hh1,
        W_fc, b_fc, out);
}

// round 8
// speedup vs baseline: 1.2738x; 1.0552x over previous
#include <cuda_runtime.h>
#include <cstddef>

// B=4096, T=256, I=6, H=64, gates=3H=192, 2 GRU layers + FC(H->1)
#define T_STEPS 256
#define I_DIM   6
#define HDIM    64
#define G3      192
#define BB      32      // batches per CTA
#define NT      256     // 64 units x 4 batch-groups
#define NBPT    8       // batches per thread
#define PW      68      // weight row pitch (floats): conflict-free LDS.128
#define NCTA    128     // 4096 / 32

typedef unsigned long long u64;

// Packed fp32x2 ops (SASS FFMA2 / FADD2-class, PTX-only)
#define FFMA2(acc, a, b) \
    asm("fma.rn.f32x2 %0, %1, %2, %0;" : "+l"(acc) : "l"(a), "l"(b))
#define ADDX2(d, a, b) \
    asm("add.rn.f32x2 %0, %1, %2;" : "=l"(d) : "l"(a), "l"(b))

union F4U { float4 f; u64 u[2]; };
union F2U { float2 f; u64 u; };

struct SmemLayout {
    float Whh0[G3 * PW];
    float Wih1[G3 * PW];
    float Whh1[G3 * PW];
    float Wih0[G3 * 8];     // pitch 8 (I=6 used) -> float2-aligned pairs
    float bih0[G3];
    float bhh0[G3];
    float bih1[G3];
    float bhh1[G3];
    float h1[2][BB][HDIM];  // ping-pong hidden state, layer 0
    float h2[2][BB][HDIM];  // ping-pong hidden state, layer 1
    float xs[2][BB][8];     // pitch 8 for float2 pairing
    float wfc[HDIM];
    float bfc;
};

__device__ __forceinline__ float sigf(float v) {
    return __fdividef(1.0f, 1.0f + __expf(-v));
}
// tanh via MUFU exp: short dependency chain.
__device__ __forceinline__ float tanhfast(float v) {
    float c = fminf(fmaxf(v, -15.0f), 15.0f);
    float e = __expf(2.0f * c);
    return __fdividef(e - 1.0f, e + 1.0f);
}
__device__ __forceinline__ float hsum(u64 p) {
    F2U t; t.u = p;
    return t.f.x + t.f.y;
}
__device__ __forceinline__ u64 packbias(float b) {
    F2U t; t.f = make_float2(b, 0.0f);
    return t.u;
}

__global__ __launch_bounds__(NT) void gru_fused_kernel(
    const float* __restrict__ x,
    const float* __restrict__ W_ih0, const float* __restrict__ W_hh0,
    const float* __restrict__ b_ih0, const float* __restrict__ b_hh0,
    const float* __restrict__ W_ih1, const float* __restrict__ W_hh1,
    const float* __restrict__ b_ih1, const float* __restrict__ b_hh1,
    const float* __restrict__ W_fc,  const float* __restrict__ b_fc,
    float* __restrict__ out)
{
    extern __shared__ float smem_raw[];
    SmemLayout& s = *reinterpret_cast<SmemLayout*>(smem_raw);

    const int tid = threadIdx.x;
    const int b0  = blockIdx.x * BB;

    // ---- Stage weights into SMEM ----
    for (int i = tid; i < G3 * HDIM; i += NT) {
        int r = i >> 6, c = i & 63;
        s.Whh0[r * PW + c] = W_hh0[i];
        s.Wih1[r * PW + c] = W_ih1[i];
        s.Whh1[r * PW + c] = W_hh1[i];
    }
    for (int i = tid; i < G3 * 8; i += NT) s.Wih0[i] = 0.0f;   // pad
    for (int i = tid; i < BB * 8 * 2; i += NT) ((float*)s.xs)[i] = 0.0f;
    __syncthreads();
    for (int i = tid; i < G3 * I_DIM; i += NT)
        s.Wih0[(i / I_DIM) * 8 + (i % I_DIM)] = W_ih0[i];
    for (int i = tid; i < G3; i += NT) {
        s.bih0[i] = b_ih0[i];
        s.bhh0[i] = b_hh0[i];
        s.bih1[i] = b_ih1[i];
        s.bhh1[i] = b_hh1[i];
    }
    for (int i = tid; i < BB * HDIM; i += NT) {
        int b = i >> 6, c = i & 63;
        s.h1[0][b][c] = 0.0f;
        s.h2[0][b][c] = 0.0f;
    }
    if (tid < HDIM) s.wfc[tid] = W_fc[tid];
    if (tid == 0)   s.bfc = b_fc[0];

    // x prefetch lanes
    const bool is_pref_lane = (tid < BB * I_DIM);
    const int  lb = is_pref_lane ? (tid / I_DIM) : 0;
    const int  li = is_pref_lane ? (tid % I_DIM) : 0;
    const float* xlane = x + (size_t)(b0 + lb) * T_STEPS * I_DIM + li;
    if (is_pref_lane) s.xs[0][lb][li] = xlane[0];
    __syncthreads();

    // Mapping: gg = hidden unit (0..63); bg = tid>>6 (0..3) -> 8 batches each.
    const int gg  = tid & 63;
    const int bg  = tid >> 6;
    const int bb0 = bg * NBPT;
    const int gr = gg, gz = gg + 64, gn = gg + 128;

    // Row base pointers (cuts per-iteration address math)
    const float* Whh0r = &s.Whh0[gr * PW];
    const float* Whh0z = &s.Whh0[gz * PW];
    const float* Whh0n = &s.Whh0[gn * PW];
    const float* Wih1r = &s.Wih1[gr * PW];
    const float* Wih1z = &s.Wih1[gz * PW];
    const float* Wih1n = &s.Wih1[gn * PW];
    const float* Whh1r = &s.Whh1[gr * PW];
    const float* Whh1z = &s.Whh1[gz * PW];
    const float* Whh1n = &s.Whh1[gn * PW];

    // Bias-seeded accumulator inits
    const u64 iR0 = packbias(s.bih0[gr] + s.bhh0[gr]);
    const u64 iZ0 = packbias(s.bih0[gz] + s.bhh0[gz]);
    const u64 iXN0 = packbias(s.bih0[gn]);
    const u64 iHN0 = packbias(s.bhh0[gn]);
    const u64 iR1 = packbias(s.bih1[gr] + s.bhh1[gr]);
    const u64 iZ1 = packbias(s.bih1[gz] + s.bhh1[gz]);
    const u64 iXN1 = packbias(s.bih1[gn]);
    const u64 iHN1 = packbias(s.bhh1[gn]);

    u64 accX[NBPT][3], accH[NBPT][3];

    for (int t = 0; t < T_STEPS; ++t) {
        const int cur = t & 1, nxt = cur ^ 1;

        float xpref = 0.0f;
        const bool do_pref = is_pref_lane && (t + 1 < T_STEPS);
        if (do_pref) xpref = xlane[(size_t)(t + 1) * I_DIM];

        // ================= Layer 0 =================
        #pragma unroll
        for (int b = 0; b < NBPT; ++b) {
            accX[b][0] = iR0;  accX[b][1] = iZ0;  accX[b][2] = iXN0;
            accH[b][0] = 0ull; accH[b][1] = 0ull; accH[b][2] = iHN0;
        }
        // input GEMV first (latency overlaps weight warm-up)
        #pragma unroll
        for (int kp = 0; kp < 3; ++kp) {
            F2U w0; w0.f = *(const float2*)&s.Wih0[gr * 8 + 2 * kp];
            F2U w1; w1.f = *(const float2*)&s.Wih0[gz * 8 + 2 * kp];
            F2U w2; w2.f = *(const float2*)&s.Wih0[gn * 8 + 2 * kp];
            #pragma unroll
            for (int b = 0; b < NBPT; ++b) {
                F2U xv; xv.f = *(const float2*)&s.xs[cur][bb0 + b][2 * kp];
                FFMA2(accX[b][0], xv.u, w0.u);
                FFMA2(accX[b][1], xv.u, w1.u);
                FFMA2(accX[b][2], xv.u, w2.u);
            }
        }
        // recurrent GEMV: weights software-pipelined one k-chunk ahead
        {
            F4U w0n, w1n, w2n;
            w0n.f = *(const float4*)&Whh0r[0];
            w1n.f = *(const float4*)&Whh0z[0];
            w2n.f = *(const float4*)&Whh0n[0];
            #pragma unroll
            for (int kc = 0; kc < 16; ++kc) {
                const int k = kc * 4;
                F4U w0 = w0n, w1 = w1n, w2 = w2n;
                if (kc < 15) {
                    w0n.f = *(const float4*)&Whh0r[k + 4];
                    w1n.f = *(const float4*)&Whh0z[k + 4];
                    w2n.f = *(const float4*)&Whh0n[k + 4];
                }
                #pragma unroll
                for (int b = 0; b < NBPT; ++b) {
                    F4U h; h.f = *(const float4*)&s.h1[cur][bb0 + b][k];
                    FFMA2(accH[b][0], h.u[0], w0.u[0]);
                    FFMA2(accH[b][0], h.u[1], w0.u[1]);
                    FFMA2(accH[b][1], h.u[0], w1.u[0]);
                    FFMA2(accH[b][1], h.u[1], w1.u[1]);
                    FFMA2(accH[b][2], h.u[0], w2.u[0]);
                    FFMA2(accH[b][2], h.u[1], w2.u[1]);
                }
            }
        }
        #pragma unroll
        for (int b = 0; b < NBPT; ++b) {
            u64 rzsum0, rzsum1;
            ADDX2(rzsum0, accX[b][0], accH[b][0]);
            ADDX2(rzsum1, accX[b][1], accH[b][1]);
            float r = sigf(hsum(rzsum0));
            float z = sigf(hsum(rzsum1));
            float n = tanhfast(fmaf(r, hsum(accH[b][2]), hsum(accX[b][2])));
            float hp = s.h1[cur][bb0 + b][gg];
            s.h1[nxt][bb0 + b][gg] = fmaf(z, hp - n, n);
        }
        if (do_pref) s.xs[nxt][lb][li] = xpref;
        __syncthreads();   // h1[nxt] complete

        // ================= Layer 1 =================
        #pragma unroll
        for (int b = 0; b < NBPT; ++b) {
            accX[b][0] = iR1;  accX[b][1] = iZ1;  accX[b][2] = iXN1;
            accH[b][0] = 0ull; accH[b][1] = 0ull; accH[b][2] = iHN1;
        }
        {
            F4U u0n, u1n, u2n, v0n, v1n, v2n;
            u0n.f = *(const float4*)&Wih1r[0];
            u1n.f = *(const float4*)&Wih1z[0];
            u2n.f = *(const float4*)&Wih1n[0];
            v0n.f = *(const float4*)&Whh1r[0];
            v1n.f = *(const float4*)&Whh1z[0];
            v2n.f = *(const float4*)&Whh1n[0];
            #pragma unroll 4
            for (int kc = 0; kc < 16; ++kc) {
                const int k = kc * 4;
                F4U u0 = u0n, u1 = u1n, u2 = u2n;
                F4U v0 = v0n, v1 = v1n, v2 = v2n;
                if (kc < 15) {
                    u0n.f = *(const float4*)&Wih1r[k + 4];
                    u1n.f = *(const float4*)&Wih1z[k + 4];
                    u2n.f = *(const float4*)&Wih1n[k + 4];
                    v0n.f = *(const float4*)&Whh1r[k + 4];
                    v1n.f = *(const float4*)&Whh1z[k + 4];
                    v2n.f = *(const float4*)&Whh1n[k + 4];
                }
                #pragma unroll
                for (int b = 0; b < NBPT; ++b) {
                    F4U p; p.f = *(const float4*)&s.h1[nxt][bb0 + b][k];
                    F4U q; q.f = *(const float4*)&s.h2[cur][bb0 + b][k];
                    FFMA2(accX[b][0], p.u[0], u0.u[0]);
                    FFMA2(accX[b][0], p.u[1], u0.u[1]);
                    FFMA2(accX[b][1], p.u[0], u1.u[0]);
                    FFMA2(accX[b][1], p.u[1], u1.u[1]);
                    FFMA2(accX[b][2], p.u[0], u2.u[0]);
                    FFMA2(accX[b][2], p.u[1], u2.u[1]);
                    FFMA2(accH[b][0], q.u[0], v0.u[0]);
                    FFMA2(accH[b][0], q.u[1], v0.u[1]);
                    FFMA2(accH[b][1], q.u[0], v1.u[0]);
                    FFMA2(accH[b][1], q.u[1], v1.u[1]);
                    FFMA2(accH[b][2], q.u[0], v2.u[0]);
                    FFMA2(accH[b][2], q.u[1], v2.u[1]);
                }
            }
        }
        #pragma unroll
        for (int b = 0; b < NBPT; ++b) {
            u64 rzsum0, rzsum1;
            ADDX2(rzsum0, accX[b][0], accH[b][0]);
            ADDX2(rzsum1, accX[b][1], accH[b][1]);
            float r = sigf(hsum(rzsum0));
            float z = sigf(hsum(rzsum1));
            float n = tanhfast(fmaf(r, hsum(accH[b][2]), hsum(accX[b][2])));
            float hp = s.h2[cur][bb0 + b][gg];
            s.h2[nxt][bb0 + b][gg] = fmaf(z, hp - n, n);
        }
        __syncthreads();   // h2[nxt] complete
    }

    // ---- Final FC ----
    const int fin = T_STEPS & 1;
    if (tid < BB) {
        float acc = s.bfc;
        #pragma unroll 8
        for (int k = 0; k < HDIM; ++k)
            acc = fmaf(s.h2[fin][tid][k], s.wfc[k], acc);
        out[b0 + tid] = acc;
    }
}

extern "C" void kernel_launch(void* const* d_in, const int* in_sizes, int n_in,
                              void* d_out, int out_size)
{
    const float* x     = (const float*)d_in[0];
    const float* W_ih0 = (const float*)d_in[1];
    const float* W_hh0 = (const float*)d_in[2];
    const float* b_ih0 = (const float*)d_in[3];
    const float* b_hh0 = (const float*)d_in[4];
    const float* W_ih1 = (const float*)d_in[5];
    const float* W_hh1 = (const float*)d_in[6];
    const float* b_ih1 = (const float*)d_in[7];
    const float* b_hh1 = (const float*)d_in[8];
    const float* W_fc  = (const float*)d_in[9];
    const float* b_fc  = (const float*)d_in[10];
    float* out = (float*)d_out;

    (void)in_sizes; (void)n_in; (void)out_size;

    static_assert(sizeof(SmemLayout) < 227 * 1024, "smem over budget");
    cudaFuncSetAttribute(gru_fused_kernel,
                         cudaFuncAttributeMaxDynamicSharedMemorySize,
                         (int)sizeof(SmemLayout));

    gru_fused_kernel<<<NCTA, NT, sizeof(SmemLayout)>>>(
        x, W_ih0, W_hh0, b_ih0, b_hh0,
        W_ih1, W_hh1, b_ih1, b_hh1,
        W_fc, b_fc, out);
}